// round 1
// baseline (speedup 1.0000x reference)
#include <cuda_runtime.h>

#define D 128
#define D4 (D / 4)
#define EPS 1e-12f
#define MAX_NODES 50000
#define MAX_EDGES 600000

// ---------------- device scratch (allocation-free) ----------------
__device__ int   g_is64;
__device__ __align__(16) float g_sim_arr[MAX_EDGES];
__device__ float g_deg[MAX_NODES];
__device__ __align__(16) float g_acc[(size_t)MAX_NODES * D];
__device__ __align__(16) float g_x1 [(size_t)MAX_NODES * D];

// ---------------- index dtype handling ----------------
// Reference does .astype(jnp.int64); without jax x64 this silently stays
// int32. Detect at runtime: int64 interpretation of the first 32 entries must
// all land in [0, num_nodes). If the payload is int32 pairs, the high words
// are random indices -> out of range as int64 with overwhelming probability.
__global__ void detect_k(const void* __restrict__ ei, int E, int nn) {
    const long long* p = (const long long*)ei;
    int ok = 1;
    for (int i = 0; i < 32; ++i) {
        long long v = p[i];
        if (v < 0 || v >= (long long)nn) { ok = 0; break; }
    }
    g_is64 = ok;
}

__device__ __forceinline__ int load_idx(const void* __restrict__ ei, int e, int E, int which) {
    if (g_is64) return (int)(((const long long*)ei)[(long long)which * E + e]);
    return ((const int*)ei)[which * E + e];
}

// ---------------- zero scratch ----------------
__global__ void zero_k(int n_acc4, int n_deg) {
    int i = blockIdx.x * blockDim.x + threadIdx.x;
    if (i < n_acc4) ((float4*)g_acc)[i] = make_float4(0.f, 0.f, 0.f, 0.f);
    if (i < n_deg)  g_deg[i] = 0.f;
}

// ---------------- edge similarity + in-degree (warp per edge) ----------------
__global__ void sim_deg_k(const float4* __restrict__ ea, const float4* __restrict__ q,
                          const void* __restrict__ ei, int E) {
    int t    = blockIdx.x * blockDim.x + threadIdx.x;
    int warp = t >> 5;
    int lane = t & 31;
    if (warp >= E) return;

    float4 a  = ea[warp * D4 + lane];
    float4 qq = q[lane];

    float dq  = a.x * qq.x + a.y * qq.y + a.z * qq.z + a.w * qq.w;
    float da  = a.x * a.x  + a.y * a.y  + a.z * a.z  + a.w * a.w;
    float dqn = qq.x * qq.x + qq.y * qq.y + qq.z * qq.z + qq.w * qq.w;

#pragma unroll
    for (int o = 16; o; o >>= 1) {
        dq  += __shfl_xor_sync(0xffffffffu, dq,  o);
        da  += __shfl_xor_sync(0xffffffffu, da,  o);
        dqn += __shfl_xor_sync(0xffffffffu, dqn, o);
    }

    if (lane == 0) {
        float sim = dq / (fmaxf(sqrtf(da), EPS) * fmaxf(sqrtf(dqn), EPS));
        g_sim_arr[warp] = sim;
        int d = load_idx(ei, warp, E, 1);
        atomicAdd(&g_deg[d], 1.0f);
    }
}

// ---------------- gather + scaled scatter-add (warp per edge) ----------------
__global__ void scatter_k(const float4* __restrict__ x, const void* __restrict__ ei, int E) {
    int t    = blockIdx.x * blockDim.x + threadIdx.x;
    int warp = t >> 5;
    int lane = t & 31;
    if (warp >= E) return;

    int   s   = load_idx(ei, warp, E, 0);
    int   d   = load_idx(ei, warp, E, 1);
    float sim = g_sim_arr[warp];

    float4 v = x[s * D4 + lane];
    v.x *= sim; v.y *= sim; v.z *= sim; v.w *= sim;

    float* addr = g_acc + ((long long)d * D + lane * 4);
    // sm_90+ vectorized reduction: 1 op for 16B, no return trip through SM.
    asm volatile("red.global.add.v4.f32 [%0], {%1,%2,%3,%4};"
                 :: "l"(addr), "f"(v.x), "f"(v.y), "f"(v.z), "f"(v.w)
                 : "memory");
}

// ---------------- residual blend (+ optional acc re-zero for next layer) ----
__global__ void combine_k(const float4* __restrict__ xin, float4* __restrict__ xout,
                          int n4, int zero_acc) {
    int i = blockIdx.x * blockDim.x + threadIdx.x;
    if (i >= n4) return;
    int   node = i >> 5;  // D4 == 32 float4 per node
    float inv  = 0.5f / fmaxf(g_deg[node], 1.0f);

    float4 a  = ((const float4*)g_acc)[i];
    float4 xi = xin[i];
    float4 o;
    o.x = 0.5f * xi.x + a.x * inv;
    o.y = 0.5f * xi.y + a.y * inv;
    o.z = 0.5f * xi.z + a.z * inv;
    o.w = 0.5f * xi.w + a.w * inv;
    xout[i] = o;

    if (zero_acc) ((float4*)g_acc)[i] = make_float4(0.f, 0.f, 0.f, 0.f);
}

// ---------------- launch ----------------
extern "C" void kernel_launch(void* const* d_in, const int* in_sizes, int n_in,
                              void* d_out, int out_size) {
    const float* x  = (const float*)d_in[0];
    const float* ea = (const float*)d_in[1];
    const float* q  = (const float*)d_in[2];
    const void*  ei = d_in[3];

    int NN = in_sizes[0] / D;   // 50000
    int E  = in_sizes[3] / 2;   // 600000 (element count is dtype-agnostic here)
    int n4 = NN * D4;           // node float4 elements

    void* x1p = nullptr;
    cudaGetSymbolAddress(&x1p, g_x1);   // query, not allocation; capture-safe

    const int TPB = 256;
    int eb = (E * 32 + TPB - 1) / TPB;            // warp-per-edge grids
    int nb = (n4 + TPB - 1) / TPB;
    int zn = n4 > NN ? n4 : NN;
    int zb = (zn + TPB - 1) / TPB;

    detect_k <<<1, 1>>>(ei, E, NN);
    zero_k   <<<zb, TPB>>>(n4, NN);
    sim_deg_k<<<eb, TPB>>>((const float4*)ea, (const float4*)q, ei, E);

    // layer 1: x -> g_x1 (and re-zero g_acc inside combine)
    scatter_k<<<eb, TPB>>>((const float4*)x, ei, E);
    combine_k<<<nb, TPB>>>((const float4*)x, (float4*)x1p, n4, 1);

    // layer 2: g_x1 -> d_out
    scatter_k<<<eb, TPB>>>((const float4*)x1p, ei, E);
    combine_k<<<nb, TPB>>>((const float4*)x1p, (float4*)d_out, n4, 0);
}

// round 2
// speedup vs baseline: 1.1777x; 1.1777x over previous
#include <cuda_runtime.h>

#define D 128
#define D4 (D / 4)
#define EPS 1e-12f
#define MAX_NODES 50000
#define MAX_EDGES 600000
#define EPW 4   // edges per warp in scatter (MLP booster)

// ---------------- device scratch (allocation-free) ----------------
__device__ int   g_is64;
__device__ __align__(16) float g_sim_arr[MAX_EDGES];
__device__ float g_deg[MAX_NODES];
__device__ __align__(16) float g_acc[(size_t)MAX_NODES * D];
__device__ __align__(16) float g_x1 [(size_t)MAX_NODES * D];

// ---------------- index dtype handling ----------------
// Reference does .astype(jnp.int64); without jax x64 it silently stays int32.
// Detect: int64 interpretation of first 32 entries must all be in range.
__global__ void detect_k(const void* __restrict__ ei, int E, int nn) {
    const long long* p = (const long long*)ei;
    int ok = 1;
    for (int i = 0; i < 32; ++i) {
        long long v = p[i];
        if (v < 0 || v >= (long long)nn) { ok = 0; break; }
    }
    g_is64 = ok;
}

__device__ __forceinline__ int load_idx(const void* __restrict__ ei, int e, int E, int which) {
    if (g_is64) return (int)(((const long long*)ei)[(long long)which * E + e]);
    return ((const int*)ei)[which * E + e];
}

// ---------------- zero scratch ----------------
__global__ void zero_k(int n_acc4, int n_deg) {
    int i = blockIdx.x * blockDim.x + threadIdx.x;
    if (i < n_acc4) ((float4*)g_acc)[i] = make_float4(0.f, 0.f, 0.f, 0.f);
    if (i < n_deg)  g_deg[i] = 0.f;
}

// ---------------- edge similarity + in-degree (warp per edge) ----------------
__global__ void sim_deg_k(const float4* __restrict__ ea, const float4* __restrict__ q,
                          const void* __restrict__ ei, int E) {
    int t    = blockIdx.x * blockDim.x + threadIdx.x;
    int warp = t >> 5;
    int lane = t & 31;
    if (warp >= E) return;

    float4 a  = ea[warp * D4 + lane];
    float4 qq = q[lane];

    float dq  = a.x * qq.x + a.y * qq.y + a.z * qq.z + a.w * qq.w;
    float da  = a.x * a.x  + a.y * a.y  + a.z * a.z  + a.w * a.w;
    float dqn = qq.x * qq.x + qq.y * qq.y + qq.z * qq.z + qq.w * qq.w;

#pragma unroll
    for (int o = 16; o; o >>= 1) {
        dq  += __shfl_xor_sync(0xffffffffu, dq,  o);
        da  += __shfl_xor_sync(0xffffffffu, da,  o);
        dqn += __shfl_xor_sync(0xffffffffu, dqn, o);
    }

    if (lane == 0) {
        float sim = dq / (fmaxf(sqrtf(da), EPS) * fmaxf(sqrtf(dqn), EPS));
        g_sim_arr[warp] = sim;
        int d = load_idx(ei, warp, E, 1);
        atomicAdd(&g_deg[d], 1.0f);
    }
}

// ---------------- gather + scaled scatter-add (warp per EPW edges) ---------
// Batch all gathers (independent LDG.128, MLP=EPW) before any red — hides
// the ~250cyc L2 latency that bound the previous single-edge-per-warp form.
__global__ void scatter_k(const float4* __restrict__ x, const void* __restrict__ ei, int E) {
    int t    = blockIdx.x * blockDim.x + threadIdx.x;
    int warp = t >> 5;
    int lane = t & 31;
    int e0   = warp * EPW;
    if (e0 >= E) return;

    float4 v[EPW];
    int    dd[EPW];
    float  sm[EPW];

#pragma unroll
    for (int j = 0; j < EPW; ++j) {
        int e = e0 + j;
        if (e < E) {
            int s = load_idx(ei, e, E, 0);       // warp-uniform broadcast load
            dd[j] = load_idx(ei, e, E, 1);
            sm[j] = g_sim_arr[e];
            v[j]  = x[(long long)s * D4 + lane]; // independent gathers -> MLP=EPW
        } else {
            dd[j] = -1;
        }
    }

#pragma unroll
    for (int j = 0; j < EPW; ++j) {
        if (dd[j] < 0) continue;
        float s = sm[j];
        float4 w = v[j];
        w.x *= s; w.y *= s; w.z *= s; w.w *= s;
        float* addr = g_acc + ((long long)dd[j] * D + lane * 4);
        asm volatile("red.global.add.v4.f32 [%0], {%1,%2,%3,%4};"
                     :: "l"(addr), "f"(w.x), "f"(w.y), "f"(w.z), "f"(w.w)
                     : "memory");
    }
}

// ---------------- residual blend (+ optional acc re-zero for next layer) ----
__global__ void combine_k(const float4* __restrict__ xin, float4* __restrict__ xout,
                          int n4, int zero_acc) {
    int i = blockIdx.x * blockDim.x + threadIdx.x;
    if (i >= n4) return;
    int   node = i >> 5;  // D4 == 32 float4 per node
    float inv  = 0.5f / fmaxf(g_deg[node], 1.0f);

    float4 a  = ((const float4*)g_acc)[i];
    float4 xi = xin[i];
    float4 o;
    o.x = 0.5f * xi.x + a.x * inv;
    o.y = 0.5f * xi.y + a.y * inv;
    o.z = 0.5f * xi.z + a.z * inv;
    o.w = 0.5f * xi.w + a.w * inv;
    xout[i] = o;

    if (zero_acc) ((float4*)g_acc)[i] = make_float4(0.f, 0.f, 0.f, 0.f);
}

// ---------------- launch ----------------
extern "C" void kernel_launch(void* const* d_in, const int* in_sizes, int n_in,
                              void* d_out, int out_size) {
    const float* x  = (const float*)d_in[0];
    const float* ea = (const float*)d_in[1];
    const float* q  = (const float*)d_in[2];
    const void*  ei = d_in[3];

    int NN = in_sizes[0] / D;   // 50000
    int E  = in_sizes[3] / 2;   // 600000
    int n4 = NN * D4;

    void* x1p = nullptr;
    cudaGetSymbolAddress(&x1p, g_x1);   // address query, capture-safe

    const int TPB = 256;
    int eb_sim  = (E * 32 + TPB - 1) / TPB;                    // warp-per-edge
    int nwarps  = (E + EPW - 1) / EPW;                         // warp-per-EPW-edges
    int eb_scat = (nwarps * 32 + TPB - 1) / TPB;
    int nb = (n4 + TPB - 1) / TPB;
    int zn = n4 > NN ? n4 : NN;
    int zb = (zn + TPB - 1) / TPB;

    detect_k <<<1, 1>>>(ei, E, NN);
    zero_k   <<<zb, TPB>>>(n4, NN);
    sim_deg_k<<<eb_sim, TPB>>>((const float4*)ea, (const float4*)q, ei, E);

    // layer 1: x -> g_x1 (re-zero g_acc inside combine)
    scatter_k<<<eb_scat, TPB>>>((const float4*)x, ei, E);
    combine_k<<<nb, TPB>>>((const float4*)x, (float4*)x1p, n4, 1);

    // layer 2: g_x1 -> d_out
    scatter_k<<<eb_scat, TPB>>>((const float4*)x1p, ei, E);
    combine_k<<<nb, TPB>>>((const float4*)x1p, (float4*)d_out, n4, 0);
}

// round 3
// speedup vs baseline: 1.8029x; 1.5309x over previous
#include <cuda_runtime.h>

#define D 128
#define D4 (D / 4)
#define EPS 1e-12f
#define MAX_NODES 50000
#define MAX_EDGES 600000
#define SCAN_B 1024

// ---------------- device scratch (allocation-free) ----------------
__device__ int   g_is64;
__device__ __align__(16) float g_sim_arr[MAX_EDGES];   // sim by original edge id
__device__ int   g_cnt[MAX_NODES];                     // in-degree (int)
__device__ int   g_cursor[MAX_NODES];                  // binning cursors
__device__ int   g_rowstart[MAX_NODES];                // CSR row starts
__device__ int   g_blocksums[64];                      // scan partials
__device__ __align__(8)  int2  g_epack[MAX_EDGES];     // CSR payload: {src, sim bits}
__device__ __align__(16) float g_x1[(size_t)MAX_NODES * D];

// ---------------- index dtype handling ----------------
// Reference does .astype(jnp.int64); without jax x64 it stays int32. Detect.
__global__ void detect_k(const void* __restrict__ ei, int E, int nn) {
    const long long* p = (const long long*)ei;
    int ok = 1;
    for (int i = 0; i < 32; ++i) {
        long long v = p[i];
        if (v < 0 || v >= (long long)nn) { ok = 0; break; }
    }
    g_is64 = ok;
}

__device__ __forceinline__ int load_idx(const void* __restrict__ ei, int e, int E, int which) {
    if (g_is64) return (int)(((const long long*)ei)[(long long)which * E + e]);
    return ((const int*)ei)[which * E + e];
}

// ---------------- zero counters ----------------
__global__ void zero_k(int nn) {
    int i = blockIdx.x * blockDim.x + threadIdx.x;
    if (i < nn) { g_cnt[i] = 0; g_cursor[i] = 0; }
}

// ------------- edge similarity + in-degree histogram (warp / 2 edges) -------
__global__ void sim_deg_k(const float4* __restrict__ ea, const float4* __restrict__ q,
                          const void* __restrict__ ei, int E) {
    int t    = blockIdx.x * blockDim.x + threadIdx.x;
    int warp = t >> 5;
    int lane = t & 31;
    int e0   = warp * 2;
    if (e0 >= E) return;
    bool has1 = (e0 + 1) < E;

    float4 qq = q[lane];
    float4 a0 = ea[(long long)e0 * D4 + lane];
    float4 a1 = has1 ? ea[(long long)(e0 + 1) * D4 + lane] : make_float4(0.f,0.f,0.f,0.f);

    float qn  = qq.x*qq.x + qq.y*qq.y + qq.z*qq.z + qq.w*qq.w;
    float dq0 = a0.x*qq.x + a0.y*qq.y + a0.z*qq.z + a0.w*qq.w;
    float da0 = a0.x*a0.x + a0.y*a0.y + a0.z*a0.z + a0.w*a0.w;
    float dq1 = a1.x*qq.x + a1.y*qq.y + a1.z*qq.z + a1.w*qq.w;
    float da1 = a1.x*a1.x + a1.y*a1.y + a1.z*a1.z + a1.w*a1.w;

#pragma unroll
    for (int o = 16; o; o >>= 1) {
        qn  += __shfl_xor_sync(0xffffffffu, qn,  o);
        dq0 += __shfl_xor_sync(0xffffffffu, dq0, o);
        da0 += __shfl_xor_sync(0xffffffffu, da0, o);
        dq1 += __shfl_xor_sync(0xffffffffu, dq1, o);
        da1 += __shfl_xor_sync(0xffffffffu, da1, o);
    }

    if (lane == 0) {
        float qinv = 1.0f / fmaxf(sqrtf(qn), EPS);
        g_sim_arr[e0] = dq0 * qinv / fmaxf(sqrtf(da0), EPS);
        atomicAdd(&g_cnt[load_idx(ei, e0, E, 1)], 1);
        if (has1) {
            g_sim_arr[e0 + 1] = dq1 * qinv / fmaxf(sqrtf(da1), EPS);
            atomicAdd(&g_cnt[load_idx(ei, e0 + 1, E, 1)], 1);
        }
    }
}

// ---------------- 3-phase exclusive scan of g_cnt -> g_rowstart -------------
__global__ void scanA_k(int nn) {
    __shared__ int sm[SCAN_B];
    int i = blockIdx.x * SCAN_B + threadIdx.x;
    int v = (i < nn) ? g_cnt[i] : 0;
    sm[threadIdx.x] = v;
    __syncthreads();
#pragma unroll
    for (int o = 1; o < SCAN_B; o <<= 1) {
        int tval = (threadIdx.x >= o) ? sm[threadIdx.x - o] : 0;
        __syncthreads();
        sm[threadIdx.x] += tval;
        __syncthreads();
    }
    int incl = sm[threadIdx.x];
    if (i < nn) g_rowstart[i] = incl - v;          // exclusive
    if (threadIdx.x == SCAN_B - 1) g_blocksums[blockIdx.x] = incl;
}

__global__ void scanB_k(int nb) {
    __shared__ int sm[64];
    int v = (threadIdx.x < nb) ? g_blocksums[threadIdx.x] : 0;
    sm[threadIdx.x] = v;
    __syncthreads();
#pragma unroll
    for (int o = 1; o < 64; o <<= 1) {
        int tval = (threadIdx.x >= o) ? sm[threadIdx.x - o] : 0;
        __syncthreads();
        sm[threadIdx.x] += tval;
        __syncthreads();
    }
    if (threadIdx.x < nb) g_blocksums[threadIdx.x] = sm[threadIdx.x] - v;  // exclusive
}

__global__ void scanC_k(int nn) {
    int i = blockIdx.x * SCAN_B + threadIdx.x;
    if (i < nn) g_rowstart[i] += g_blocksums[blockIdx.x];
}

// ---------------- bin edges into CSR slots (thread per edge) ----------------
__global__ void bin_k(const void* __restrict__ ei, int E) {
    int e = blockIdx.x * blockDim.x + threadIdx.x;
    if (e >= E) return;
    int s = load_idx(ei, e, E, 0);
    int d = load_idx(ei, e, E, 1);
    int pos = g_rowstart[d] + atomicAdd(&g_cursor[d], 1);
    int2 p;
    p.x = s;
    p.y = __float_as_int(g_sim_arr[e]);
    g_epack[pos] = p;
}

// -------- gather aggregation + fused residual blend (warp per node) ---------
__global__ void agg_k(const float4* __restrict__ xin, float4* __restrict__ xout, int nn) {
    int t    = blockIdx.x * blockDim.x + threadIdx.x;
    int node = t >> 5;
    int lane = t & 31;
    if (node >= nn) return;

    int start = g_rowstart[node];
    int cnt   = g_cnt[node];
    int end   = start + cnt;

    float4 acc = make_float4(0.f, 0.f, 0.f, 0.f);

    for (int base = start; base < end; base += 32) {
        int n = min(32, end - base);
        // one coalesced 256B read serves up to 32 edges
        int2 mp = (lane < n) ? g_epack[base + lane] : make_int2(0, 0);

        int j = 0;
        for (; j + 4 <= n; j += 4) {
            int   s0 = __shfl_sync(0xffffffffu, mp.x, j);
            int   s1 = __shfl_sync(0xffffffffu, mp.x, j + 1);
            int   s2 = __shfl_sync(0xffffffffu, mp.x, j + 2);
            int   s3 = __shfl_sync(0xffffffffu, mp.x, j + 3);
            float m0 = __int_as_float(__shfl_sync(0xffffffffu, mp.y, j));
            float m1 = __int_as_float(__shfl_sync(0xffffffffu, mp.y, j + 1));
            float m2 = __int_as_float(__shfl_sync(0xffffffffu, mp.y, j + 2));
            float m3 = __int_as_float(__shfl_sync(0xffffffffu, mp.y, j + 3));
            // 4 independent gathers -> MLP=4 before any consume
            float4 v0 = xin[(long long)s0 * D4 + lane];
            float4 v1 = xin[(long long)s1 * D4 + lane];
            float4 v2 = xin[(long long)s2 * D4 + lane];
            float4 v3 = xin[(long long)s3 * D4 + lane];
            acc.x += m0*v0.x + m1*v1.x + m2*v2.x + m3*v3.x;
            acc.y += m0*v0.y + m1*v1.y + m2*v2.y + m3*v3.y;
            acc.z += m0*v0.z + m1*v1.z + m2*v2.z + m3*v3.z;
            acc.w += m0*v0.w + m1*v1.w + m2*v2.w + m3*v3.w;
        }
        for (; j < n; ++j) {
            int   s = __shfl_sync(0xffffffffu, mp.x, j);
            float m = __int_as_float(__shfl_sync(0xffffffffu, mp.y, j));
            float4 v = xin[(long long)s * D4 + lane];
            acc.x += m*v.x; acc.y += m*v.y; acc.z += m*v.z; acc.w += m*v.w;
        }
    }

    float inv = 0.5f / fmaxf((float)cnt, 1.0f);
    float4 xi = xin[(long long)node * D4 + lane];
    float4 o;
    o.x = 0.5f * xi.x + acc.x * inv;
    o.y = 0.5f * xi.y + acc.y * inv;
    o.z = 0.5f * xi.z + acc.z * inv;
    o.w = 0.5f * xi.w + acc.w * inv;
    xout[(long long)node * D4 + lane] = o;
}

// ---------------- launch ----------------
extern "C" void kernel_launch(void* const* d_in, const int* in_sizes, int n_in,
                              void* d_out, int out_size) {
    const float* x  = (const float*)d_in[0];
    const float* ea = (const float*)d_in[1];
    const float* q  = (const float*)d_in[2];
    const void*  ei = d_in[3];

    int NN = in_sizes[0] / D;   // 50000
    int E  = in_sizes[3] / 2;   // 600000

    void* x1p = nullptr;
    cudaGetSymbolAddress(&x1p, g_x1);   // address query, capture-safe

    const int TPB = 256;
    int zb      = (NN + TPB - 1) / TPB;
    int simw    = (E + 1) / 2;                       // warps (2 edges each)
    int eb_sim  = (simw * 32 + TPB - 1) / TPB;
    int nbscan  = (NN + SCAN_B - 1) / SCAN_B;        // 49 blocks (<=64)
    int eb_bin  = (E + TPB - 1) / TPB;
    int nb_agg  = (NN * 32 + TPB - 1) / TPB;

    detect_k <<<1, 1>>>(ei, E, NN);
    zero_k   <<<zb, TPB>>>(NN);
    sim_deg_k<<<eb_sim, TPB>>>((const float4*)ea, (const float4*)q, ei, E);

    scanA_k<<<nbscan, SCAN_B>>>(NN);
    scanB_k<<<1, 64>>>(nbscan);
    scanC_k<<<nbscan, SCAN_B>>>(NN);
    bin_k  <<<eb_bin, TPB>>>(ei, E);

    // layer 1: x -> g_x1
    agg_k<<<nb_agg, TPB>>>((const float4*)x, (float4*)x1p, NN);
    // layer 2: g_x1 -> d_out
    agg_k<<<nb_agg, TPB>>>((const float4*)x1p, (float4*)d_out, NN);
}

// round 4
// speedup vs baseline: 1.8803x; 1.0429x over previous
#include <cuda_runtime.h>

#define D 128
#define D4 (D / 4)
#define EPS 1e-12f
#define MAX_NODES 50000
#define MAX_EDGES 600000
#define SCAN_B 1024

// ---------------- device scratch (allocation-free) ----------------
__device__ int   g_is64;
__device__ __align__(16) float g_sim_arr[MAX_EDGES];   // sim by original edge id
__device__ int   g_cnt[MAX_NODES];                     // in-degree
__device__ int   g_cursor[MAX_NODES];                  // binning cursors
__device__ int   g_rowstart[MAX_NODES];                // CSR row starts
__device__ int   g_blocksums[64];                      // scan partials
__device__ __align__(8)  int2  g_epack[MAX_EDGES];     // CSR payload: {src, sim bits}
__device__ __align__(16) float g_x1[(size_t)MAX_NODES * D];

// ---------------- index dtype detection (one warp, parallel loads) ---------
// Reference does .astype(jnp.int64); without jax x64 it stays int32.
__global__ void detect_k(const void* __restrict__ ei, int E, int nn) {
    const long long* p = (const long long*)ei;
    int lane = threadIdx.x;
    long long v = p[lane];                       // 32 independent loads, MLP=32
    int bad = (v < 0) || (v >= (long long)nn);
    unsigned m = __ballot_sync(0xffffffffu, bad);
    if (lane == 0) g_is64 = (m == 0);
}

__device__ __forceinline__ int load_idx(const void* __restrict__ ei, int e, int E, int which) {
    if (g_is64) return (int)(((const long long*)ei)[(long long)which * E + e]);
    return ((const int*)ei)[which * E + e];
}

// ---------------- zero counters ----------------
__global__ void zero_k(int nn) {
    int i = blockIdx.x * blockDim.x + threadIdx.x;
    if (i < nn) { g_cnt[i] = 0; g_cursor[i] = 0; }
}

// ------- edge similarity + in-degree histogram (warp / 4 edges, MLP=4) ------
__global__ void sim_deg_k(const float4* __restrict__ ea, const float4* __restrict__ q,
                          const void* __restrict__ ei, int E) {
    int t    = blockIdx.x * blockDim.x + threadIdx.x;
    int warp = t >> 5;
    int lane = t & 31;
    int e0   = warp * 4;
    if (e0 >= E) return;

    float4 qq = q[lane];
    float  qn = qq.x*qq.x + qq.y*qq.y + qq.z*qq.z + qq.w*qq.w;

    float dq[4], da[4];
#pragma unroll
    for (int j = 0; j < 4; ++j) {
        int e = e0 + j;
        float4 a = (e < E) ? ea[(long long)e * D4 + lane] : make_float4(0.f,0.f,0.f,0.f);
        dq[j] = a.x*qq.x + a.y*qq.y + a.z*qq.z + a.w*qq.w;
        da[j] = a.x*a.x  + a.y*a.y  + a.z*a.z  + a.w*a.w;
    }

#pragma unroll
    for (int o = 16; o; o >>= 1) {
        qn += __shfl_xor_sync(0xffffffffu, qn, o);
#pragma unroll
        for (int j = 0; j < 4; ++j) {
            dq[j] += __shfl_xor_sync(0xffffffffu, dq[j], o);
            da[j] += __shfl_xor_sync(0xffffffffu, da[j], o);
        }
    }

    if (lane == 0) {
        float qinv = 1.0f / fmaxf(sqrtf(qn), EPS);
#pragma unroll
        for (int j = 0; j < 4; ++j) {
            int e = e0 + j;
            if (e < E) {
                g_sim_arr[e] = dq[j] * qinv / fmaxf(sqrtf(da[j]), EPS);
                atomicAdd(&g_cnt[load_idx(ei, e, E, 1)], 1);
            }
        }
    }
}

// ---------------- shuffle-based exclusive scan: g_cnt -> g_rowstart ---------
__global__ void scanA_k(int nn) {
    __shared__ int wsum[32];
    int i    = blockIdx.x * SCAN_B + threadIdx.x;
    int lane = threadIdx.x & 31;
    int wid  = threadIdx.x >> 5;
    int v    = (i < nn) ? g_cnt[i] : 0;

    int incl = v;
#pragma unroll
    for (int o = 1; o < 32; o <<= 1) {
        int tv = __shfl_up_sync(0xffffffffu, incl, o);
        if (lane >= o) incl += tv;
    }
    if (lane == 31) wsum[wid] = incl;
    __syncthreads();
    if (wid == 0) {
        int w  = wsum[lane];
        int wi = w;
#pragma unroll
        for (int o = 1; o < 32; o <<= 1) {
            int tv = __shfl_up_sync(0xffffffffu, wi, o);
            if (lane >= o) wi += tv;
        }
        wsum[lane] = wi - w;                       // exclusive warp offsets
        if (lane == 31) g_blocksums[blockIdx.x] = wi;
    }
    __syncthreads();
    if (i < nn) g_rowstart[i] = incl - v + wsum[wid];
}

__global__ void scanB_k(int nb) {   // <=64 partials, one warp, 2 per lane
    int lane = threadIdx.x;
    int v0 = (2*lane     < nb) ? g_blocksums[2*lane]     : 0;
    int v1 = (2*lane + 1 < nb) ? g_blocksums[2*lane + 1] : 0;
    int s  = v0 + v1;
    int incl = s;
#pragma unroll
    for (int o = 1; o < 32; o <<= 1) {
        int tv = __shfl_up_sync(0xffffffffu, incl, o);
        if (lane >= o) incl += tv;
    }
    int excl = incl - s;
    if (2*lane     < nb) g_blocksums[2*lane]     = excl;
    if (2*lane + 1 < nb) g_blocksums[2*lane + 1] = excl + v0;
}

__global__ void scanC_k(int nn) {
    int i = blockIdx.x * SCAN_B + threadIdx.x;
    if (i < nn) g_rowstart[i] += g_blocksums[blockIdx.x];
}

// ---------------- bin edges into CSR slots (thread per edge) ----------------
__global__ void bin_k(const void* __restrict__ ei, int E) {
    int e = blockIdx.x * blockDim.x + threadIdx.x;
    if (e >= E) return;
    int s = load_idx(ei, e, E, 0);
    int d = load_idx(ei, e, E, 1);
    int pos = g_rowstart[d] + atomicAdd(&g_cursor[d], 1);
    int2 p;
    p.x = s;
    p.y = __float_as_int(g_sim_arr[e]);
    g_epack[pos] = p;
}

// -------- gather aggregation + fused residual blend (warp per node) ---------
__global__ void agg_k(const float4* __restrict__ xin, float4* __restrict__ xout, int nn) {
    int t    = blockIdx.x * blockDim.x + threadIdx.x;
    int node = t >> 5;
    int lane = t & 31;
    if (node >= nn) return;

    int start = g_rowstart[node];
    int cnt   = g_cnt[node];
    int end   = start + cnt;

    float accx = 0.f, accy = 0.f, accz = 0.f, accw = 0.f;

    for (int base = start; base < end; base += 32) {
        int n = min(32, end - base);
        int2 mp = (lane < n) ? g_epack[base + lane] : make_int2(0, 0);

        int j = 0;
        for (; j + 8 <= n; j += 8) {
            int   s[8];
            float m[8];
            float4 v[8];
#pragma unroll
            for (int k = 0; k < 8; ++k) {
                s[k] = __shfl_sync(0xffffffffu, mp.x, j + k);
                m[k] = __int_as_float(__shfl_sync(0xffffffffu, mp.y, j + k));
            }
#pragma unroll
            for (int k = 0; k < 8; ++k)     // 8 independent LDG.128 -> MLP=8
                v[k] = xin[(long long)s[k] * D4 + lane];
#pragma unroll
            for (int k = 0; k < 8; ++k) {
                accx += m[k]*v[k].x; accy += m[k]*v[k].y;
                accz += m[k]*v[k].z; accw += m[k]*v[k].w;
            }
        }
        for (; j + 4 <= n; j += 4) {
            int   s[4];
            float m[4];
            float4 v[4];
#pragma unroll
            for (int k = 0; k < 4; ++k) {
                s[k] = __shfl_sync(0xffffffffu, mp.x, j + k);
                m[k] = __int_as_float(__shfl_sync(0xffffffffu, mp.y, j + k));
            }
#pragma unroll
            for (int k = 0; k < 4; ++k)
                v[k] = xin[(long long)s[k] * D4 + lane];
#pragma unroll
            for (int k = 0; k < 4; ++k) {
                accx += m[k]*v[k].x; accy += m[k]*v[k].y;
                accz += m[k]*v[k].z; accw += m[k]*v[k].w;
            }
        }
        for (; j < n; ++j) {
            int   s = __shfl_sync(0xffffffffu, mp.x, j);
            float m = __int_as_float(__shfl_sync(0xffffffffu, mp.y, j));
            float4 v = xin[(long long)s * D4 + lane];
            accx += m*v.x; accy += m*v.y; accz += m*v.z; accw += m*v.w;
        }
    }

    float inv = 0.5f / fmaxf((float)cnt, 1.0f);
    float4 xi = xin[(long long)node * D4 + lane];
    float4 o;
    o.x = 0.5f * xi.x + accx * inv;
    o.y = 0.5f * xi.y + accy * inv;
    o.z = 0.5f * xi.z + accz * inv;
    o.w = 0.5f * xi.w + accw * inv;
    xout[(long long)node * D4 + lane] = o;
}

// ---------------- launch ----------------
extern "C" void kernel_launch(void* const* d_in, const int* in_sizes, int n_in,
                              void* d_out, int out_size) {
    const float* x  = (const float*)d_in[0];
    const float* ea = (const float*)d_in[1];
    const float* q  = (const float*)d_in[2];
    const void*  ei = d_in[3];

    int NN = in_sizes[0] / D;   // 50000
    int E  = in_sizes[3] / 2;   // 600000

    void* x1p = nullptr;
    cudaGetSymbolAddress(&x1p, g_x1);   // address query, capture-safe

    const int TPB = 256;
    int zb      = (NN + TPB - 1) / TPB;
    int simw    = (E + 3) / 4;                       // warps (4 edges each)
    int eb_sim  = (simw * 32 + TPB - 1) / TPB;
    int nbscan  = (NN + SCAN_B - 1) / SCAN_B;        // 49 blocks (<=64)
    int eb_bin  = (E + TPB - 1) / TPB;
    int nb_agg  = (NN * 32 + TPB - 1) / TPB;

    detect_k <<<1, 32>>>(ei, E, NN);
    zero_k   <<<zb, TPB>>>(NN);
    sim_deg_k<<<eb_sim, TPB>>>((const float4*)ea, (const float4*)q, ei, E);

    scanA_k<<<nbscan, SCAN_B>>>(NN);
    scanB_k<<<1, 32>>>(nbscan);
    scanC_k<<<nbscan, SCAN_B>>>(NN);
    bin_k  <<<eb_bin, TPB>>>(ei, E);

    // layer 1: x -> g_x1
    agg_k<<<nb_agg, TPB>>>((const float4*)x, (float4*)x1p, NN);
    // layer 2: g_x1 -> d_out
    agg_k<<<nb_agg, TPB>>>((const float4*)x1p, (float4*)d_out, NN);
}